// round 10
// baseline (speedup 1.0000x reference)
#include <cuda_runtime.h>
#include <math.h>

#define N_COMBOS   64
#define N_STRUCTS  512
#define HID        1024
#define BATCH      2048
#define NITERS     60
#define POW_ITERS  30

#define MAX_NNZ_G  32768
#define MAX_LR     96
#define COLCAP     8192
#define ROWS_PER_BLK 8

// dynamic smem layout (bytes)
#define SX_STRIDE   544                    // floats per xbar copy (512 + 32 pad/sentinel)
#define SY_STRIDE   96                     // floats per y1 copy (64 + 32 pad/sentinel)
#define OFF_SX      0                                        // 8 rows x 2 copies x 544 f = 34816 B
#define OFF_SY      (OFF_SX + ROWS_PER_BLK * 2 * SX_STRIDE * 4)   // 8 x 4 x 96 f = 12288 B
#define OFF_ELLR    (OFF_SY + ROWS_PER_BLK * 4 * SY_STRIDE * 4)   // 96*32 u32 = 12288 B
#define OFF_CI4     (OFF_ELLR + MAX_LR * 32 * 4)                  // 8192 B
#define OFF_CP4     (OFF_CI4 + COLCAP)                            // 516 u16 = 1032 B
#define DYN_SMEM    (OFF_CP4 + 1040)

// ---------------- device scratch ----------------
__device__ float g_A1[BATCH * HID];
__device__ float g_A2[BATCH * HID];
__device__ float g_Z [BATCH * N_STRUCTS];
__device__ float g_tau;

__device__ int            g_row_ptr[N_COMBOS + 1];
__device__ unsigned short g_row_idx[MAX_NNZ_G];
__device__ int            g_col_ptr[N_STRUCTS + 1];
__device__ unsigned char  g_col_idx[MAX_NNZ_G];

__device__ unsigned int   g_ellr[MAX_LR * 32];   // [p][lane]: idx(row=lane) | idx(row=lane+32)<<16 ; sentinel 512
__device__ int            g_len_ellr;
__device__ unsigned short g_cp4[N_STRUCTS + 1];  // padded (mult of 4) CSC offsets
__device__ unsigned char  g_ci4[COLCAP];         // padded CSC col indices; sentinel 64

// ---------------- prep (R7, unchanged) ----------------
__global__ __launch_bounds__(512) void prep_kernel(const float* __restrict__ S) {
    __shared__ int cnt[N_STRUCTS];
    int tid = threadIdx.x;

    if (tid < N_COMBOS) {
        int c = 0;
        for (int j = 0; j < N_STRUCTS; j++) if (S[tid * N_STRUCTS + j] != 0.f) c++;
        cnt[tid] = c;
    }
    __syncthreads();
    if (tid == 0) {
        int acc = 0;
        for (int i = 0; i < N_COMBOS; i++) { g_row_ptr[i] = acc; acc += cnt[i]; }
        g_row_ptr[N_COMBOS] = acc;
    }
    __syncthreads();
    if (tid < N_COMBOS) {
        int p = g_row_ptr[tid];
        for (int j = 0; j < N_STRUCTS; j++)
            if (S[tid * N_STRUCTS + j] != 0.f) g_row_idx[p++] = (unsigned short)j;
    }
    __syncthreads();

    {
        int c = 0;
        for (int i = 0; i < N_COMBOS; i++) if (S[i * N_STRUCTS + tid] != 0.f) c++;
        cnt[tid] = c;
    }
    __syncthreads();
    if (tid == 0) {
        int acc = 0;
        for (int j = 0; j < N_STRUCTS; j++) { g_col_ptr[j] = acc; acc += cnt[j]; }
        g_col_ptr[N_STRUCTS] = acc;
    }
    __syncthreads();
    {
        int p = g_col_ptr[tid];
        for (int i = 0; i < N_COMBOS; i++)
            if (S[i * N_STRUCTS + tid] != 0.f) g_col_idx[p++] = (unsigned char)i;
    }
    __syncthreads();

    if (tid < 32) {
        int ra = g_row_ptr[tid],      la = g_row_ptr[tid + 1]  - ra;
        int rb = g_row_ptr[tid + 32], lb = g_row_ptr[tid + 33] - rb;
        int L = la > lb ? la : lb;
        if (L > MAX_LR) L = MAX_LR;
        for (int p = 0; p < MAX_LR; p++) {
            unsigned a = (p < la) ? g_row_idx[ra + p] : 512u;
            unsigned b = (p < lb) ? g_row_idx[rb + p] : 512u;
            g_ellr[p * 32 + tid] = a | (b << 16);
        }
        #pragma unroll
        for (int o = 16; o; o >>= 1) { int v = __shfl_xor_sync(0xffffffffu, L, o); L = v > L ? v : L; }
        if (tid == 0) g_len_ellr = L;
    }
    if (tid == 0) {
        int acc = 0;
        for (int j = 0; j < N_STRUCTS; j++) {
            g_cp4[j] = (unsigned short)acc;
            int l = g_col_ptr[j + 1] - g_col_ptr[j];
            acc += (l + 3) & ~3;
        }
        g_cp4[N_STRUCTS] = (unsigned short)acc;
    }
    __syncthreads();
    {
        int j = tid;
        int o = g_cp4[j];
        int base = g_col_ptr[j];
        int l = g_col_ptr[j + 1] - base;
        int pl = (l + 3) & ~3;
        for (int p = 0; p < pl && (o + p) < COLCAP; p++)
            g_ci4[o + p] = (p < l) ? g_col_idx[base + p] : (unsigned char)64;
    }
}

// ---------------- power iteration (unchanged) ----------------
__global__ __launch_bounds__(512) void power_kernel() {
    __shared__ float v[N_STRUCTS];
    __shared__ float t[N_COMBOS];
    __shared__ float red[16];
    int tid = threadIdx.x;

    v[tid] = 1.0f / sqrtf((float)N_STRUCTS);
    __syncthreads();

    for (int it = 0; it < POW_ITERS; it++) {
        if (tid < N_COMBOS) {
            float s = 0.f;
            int pe = g_row_ptr[tid + 1];
            for (int p = g_row_ptr[tid]; p < pe; p++) s += v[g_row_idx[p]];
            t[tid] = s;
        }
        __syncthreads();
        float w;
        {
            float s = 0.f;
            int pe = g_col_ptr[tid + 1];
            for (int p = g_col_ptr[tid]; p < pe; p++) s += t[g_col_idx[p]];
            w = s + v[tid];
        }
        float sq = w * w;
        #pragma unroll
        for (int o = 16; o; o >>= 1) sq += __shfl_xor_sync(0xffffffffu, sq, o);
        if ((tid & 31) == 0) red[tid >> 5] = sq;
        __syncthreads();
        float tot = 0.f;
        #pragma unroll
        for (int k = 0; k < 16; k++) tot += red[k];
        v[tid] = w / sqrtf(tot);
        __syncthreads();
    }

    if (tid < N_COMBOS) {
        float s = 0.f;
        int pe = g_row_ptr[tid + 1];
        for (int p = g_row_ptr[tid]; p < pe; p++) s += v[g_row_idx[p]];
        t[tid] = s;
    }
    __syncthreads();
    float w;
    {
        float s = 0.f;
        int pe = g_col_ptr[tid + 1];
        for (int p = g_col_ptr[tid]; p < pe; p++) s += t[g_col_idx[p]];
        w = s + v[tid];
    }
    float dq = v[tid] * w;
    #pragma unroll
    for (int o = 16; o; o >>= 1) dq += __shfl_xor_sync(0xffffffffu, dq, o);
    if ((tid & 31) == 0) red[tid >> 5] = dq;
    __syncthreads();
    if (tid == 0) {
        float tot = 0.f;
        #pragma unroll
        for (int k = 0; k < 16; k++) tot += red[k];
        g_tau = 0.9f / sqrtf(tot);
    }
}

// ---------------- GEMM + bias + relu (64x64x16, 128 threads, 8x4) — R7's 132us version ----------------
__global__ __launch_bounds__(128) void gemm_bias_relu(
    const float* __restrict__ A, const float* __restrict__ B,
    const float* __restrict__ bias, float* __restrict__ C,
    int M, int N, int K)
{
    const int BK = 16;
    __shared__ __align__(16) float As[BK][64];
    __shared__ __align__(16) float Bs[BK][64];

    const int tid = threadIdx.x;
    const int bm = blockIdx.y * 64;
    const int bn = blockIdx.x * 64;

    const int a_r = tid >> 1, a_c = (tid & 1) * 8;
    const int b_r = tid >> 3, b_c = (tid & 7) * 8;
    const int tx = tid & 15, ty = tid >> 4;

    float acc[8][4];
    #pragma unroll
    for (int i = 0; i < 8; i++)
        #pragma unroll
        for (int j = 0; j < 4; j++) acc[i][j] = 0.f;

    for (int k0 = 0; k0 < K; k0 += BK) {
        float4 av0 = *(const float4*)&A[(size_t)(bm + a_r) * K + k0 + a_c];
        float4 av1 = *(const float4*)&A[(size_t)(bm + a_r) * K + k0 + a_c + 4];
        As[a_c + 0][a_r] = av0.x; As[a_c + 1][a_r] = av0.y;
        As[a_c + 2][a_r] = av0.z; As[a_c + 3][a_r] = av0.w;
        As[a_c + 4][a_r] = av1.x; As[a_c + 5][a_r] = av1.y;
        As[a_c + 6][a_r] = av1.z; As[a_c + 7][a_r] = av1.w;
        float4 bv0 = *(const float4*)&B[(size_t)(k0 + b_r) * N + bn + b_c];
        float4 bv1 = *(const float4*)&B[(size_t)(k0 + b_r) * N + bn + b_c + 4];
        *(float4*)&Bs[b_r][b_c] = bv0;
        *(float4*)&Bs[b_r][b_c + 4] = bv1;
        __syncthreads();

        #pragma unroll
        for (int k = 0; k < BK; k++) {
            float4 a0 = *(const float4*)&As[k][ty * 8];
            float4 a1 = *(const float4*)&As[k][ty * 8 + 4];
            float4 b0 = *(const float4*)&Bs[k][tx * 4];
            float a[8] = {a0.x, a0.y, a0.z, a0.w, a1.x, a1.y, a1.z, a1.w};
            float bb[4] = {b0.x, b0.y, b0.z, b0.w};
            #pragma unroll
            for (int i = 0; i < 8; i++)
                #pragma unroll
                for (int j = 0; j < 4; j++)
                    acc[i][j] = fmaf(a[i], bb[j], acc[i][j]);
        }
        __syncthreads();
    }

    #pragma unroll
    for (int j = 0; j < 4; j++) {
        float bb = bias[bn + tx * 4 + j];
        #pragma unroll
        for (int i = 0; i < 8; i++) {
            float r = acc[i][j] + bb;
            C[(size_t)(bm + ty * 8 + i) * N + bn + tx * 4 + j] = r > 0.f ? r : 0.f;
        }
    }
}

// ---------------- PDHG: warp-per-row + bank-replicated xbar/y1 ----------------
__global__ __launch_bounds__(256, 2) void pdhg_warp_kernel(
    const float* __restrict__ Zg, const float* __restrict__ Xg,
    float* __restrict__ out)
{
    extern __shared__ __align__(16) char dyn[];
    float*          sx_all  = (float*)(dyn + OFF_SX);    // [8][2][544]
    float*          sy_all  = (float*)(dyn + OFF_SY);    // [8][4][96]
    unsigned int*   s_ellr  = (unsigned int*)(dyn + OFF_ELLR);
    unsigned char*  s_ci4   = (unsigned char*)(dyn + OFF_CI4);
    unsigned short* s_cp4   = (unsigned short*)(dyn + OFF_CP4);

    const int tid = threadIdx.x;
    const int w   = tid >> 5;
    const int l   = tid & 31;
    const int row = blockIdx.x * ROWS_PER_BLK + w;
    const float tau = g_tau;
    const float sigma = tau;
    const int LEN = g_len_ellr;

    // structure copies
    for (int p = tid; p < LEN * 32; p += 256) s_ellr[p] = g_ellr[p];
    for (int p = tid; p <= N_STRUCTS; p += 256) s_cp4[p] = g_cp4[p];
    {
        int tot = (g_cp4[N_STRUCTS] + 3) & ~3;
        for (int p = tid * 4; p < tot; p += 1024)
            *(unsigned int*)&s_ci4[p] = *(const unsigned int*)&g_ci4[p];
    }
    // zero state (incl. sentinel pads)
    for (int p = tid; p < ROWS_PER_BLK * 2 * SX_STRIDE; p += 256) sx_all[p] = 0.f;
    for (int p = tid; p < ROWS_PER_BLK * 4 * SY_STRIDE; p += 256) sy_all[p] = 0.f;

    // per-warp pointers
    float* sx0 = sx_all + w * 2 * SX_STRIDE;       // copy0: value of col j at slot j
    float* sx1 = sx0 + SX_STRIDE;                  // copy1: value of col j at slot j^16
    float* syw = sy_all + w * 4 * SY_STRIDE;       // 4 copies: value of row i at slot i^(8c)
    const int  h2   = l >> 4;                      // xbar copy selector for reads
    const unsigned xxor = h2 << 4;
    float* sxr = h2 ? sx1 : sx0;
    const int  gq   = l >> 3;                      // y1 copy selector for reads
    const unsigned yxor = gq << 3;
    float* syr = syw + gq * SY_STRIDE;

    const float B0 = Xg[row * N_COMBOS + l];
    const float B1 = Xg[row * N_COMBOS + l + 32];
    float yy0 = 0.f, yy1 = 0.f;

    float Zr[16], xr[16], y2[16], xb[16], dq[16];
    #pragma unroll
    for (int q = 0; q < 16; q++) {
        int j = q * 32 + l;
        Zr[q] = Zg[(size_t)row * N_STRUCTS + j];
        xr[q] = 0.f; y2[q] = 0.f; xb[q] = 0.f;
    }
    __syncthreads();

    for (int it = 0; it < NITERS; it++) {
        // ---- y1 gather (ELL, x2 unroll, replicated xbar) ----
        float s0a = 0.f, s1a = 0.f, s0b = 0.f, s1b = 0.f;
        int p = 0;
        for (; p + 2 <= LEN; p += 2) {
            unsigned ua = s_ellr[p * 32 + l];
            unsigned ub = s_ellr[(p + 1) * 32 + l];
            float va0 = sxr[(ua & 0xffffu) ^ xxor];
            float va1 = sxr[(ua >> 16) ^ xxor];
            float vb0 = sxr[(ub & 0xffffu) ^ xxor];
            float vb1 = sxr[(ub >> 16) ^ xxor];
            s0a += va0; s1a += va1;
            s0b += vb0; s1b += vb1;
        }
        if (p < LEN) {
            unsigned ua = s_ellr[p * 32 + l];
            s0a += sxr[(ua & 0xffffu) ^ xxor];
            s1a += sxr[(ua >> 16) ^ xxor];
        }
        float s0 = s0a + s0b, s1 = s1a + s1b;
        yy0 = fmaxf(fmaf(sigma, s0 - B0, yy0), 0.f);
        yy1 = fmaxf(fmaf(sigma, s1 - B1, yy1), 0.f);
        #pragma unroll
        for (int c = 0; c < 4; c++) {
            syw[c * SY_STRIDE + (l ^ (c << 3))] = yy0;
            syw[c * SY_STRIDE + ((l ^ (c << 3)) + 32)] = yy1;
        }

        // ---- y2 update (registers) ----
        #pragma unroll
        for (int q = 0; q < 16; q++)
            y2[q] = fmaxf(fmaf(-sigma, xb[q], y2[q]), 0.f);
        __syncwarp();

        // ---- g = S^T y1 - y2 ; prox (replicated y1) ----
        float sumsq = 0.f;
        #pragma unroll
        for (int q = 0; q < 16; q++) {
            int j = q * 32 + l;
            int o = s_cp4[j], e = s_cp4[j + 1];
            float g = 0.f;
            for (int pp = o; pp < e; pp += 4) {
                unsigned w4 = *(const unsigned int*)&s_ci4[pp];
                g += syr[(w4 & 255u) ^ yxor] + syr[((w4 >> 8) & 255u) ^ yxor]
                   + syr[((w4 >> 16) & 255u) ^ yxor] + syr[(w4 >> 24) ^ yxor];
            }
            g -= y2[q];
            float v = fmaf(-tau, g, xr[q]);
            float d = v + tau - Zr[q];
            dq[q] = d;
            sumsq = fmaf(d, d, sumsq);
        }
        #pragma unroll
        for (int o = 16; o; o >>= 1) sumsq += __shfl_xor_sync(0xffffffffu, sumsq, o);
        float nrm = sqrtf(sumsq);
        float scale = fmaxf(1.f - tau / fmaxf(nrm, 1e-12f), 0.f);

        #pragma unroll
        for (int q = 0; q < 16; q++) {
            int j = q * 32 + l;
            float xn  = fmaf(scale, dq[q], Zr[q]);
            float xbv = 2.f * xn - xr[q];
            xr[q] = xn;
            xb[q] = xbv;
            sx0[j] = xbv;
            sx1[j ^ 16] = xbv;
        }
        __syncwarp();
    }

    #pragma unroll
    for (int q = 0; q < 16; q++)
        out[(size_t)row * N_STRUCTS + q * 32 + l] = xr[q];
}

// ---------------- launch ----------------
extern "C" void kernel_launch(void* const* d_in, const int* in_sizes, int n_in,
                              void* d_out, int out_size) {
    const float* X  = (const float*)d_in[0];
    const float* W1 = (const float*)d_in[1];
    const float* b1 = (const float*)d_in[2];
    const float* W2 = (const float*)d_in[3];
    const float* b2 = (const float*)d_in[4];
    const float* W3 = (const float*)d_in[5];
    const float* b3 = (const float*)d_in[6];
    const float* S  = (const float*)d_in[7];
    float* out = (float*)d_out;

    float *A1, *A2, *Z;
    cudaGetSymbolAddress((void**)&A1, g_A1);
    cudaGetSymbolAddress((void**)&A2, g_A2);
    cudaGetSymbolAddress((void**)&Z,  g_Z);

    static int smem_set = 0;
    if (!smem_set) {
        cudaFuncSetAttribute(pdhg_warp_kernel,
                             cudaFuncAttributeMaxDynamicSharedMemorySize, DYN_SMEM);
        smem_set = 1;
    }

    prep_kernel<<<1, 512>>>(S);
    power_kernel<<<1, 512>>>();

    gemm_bias_relu<<<dim3(HID / 64, BATCH / 64), 128>>>(X, W1, b1, A1, BATCH, HID, N_COMBOS);
    gemm_bias_relu<<<dim3(HID / 64, BATCH / 64), 128>>>(A1, W2, b2, A2, BATCH, HID, HID);
    gemm_bias_relu<<<dim3(N_STRUCTS / 64, BATCH / 64), 128>>>(A2, W3, b3, Z, BATCH, N_STRUCTS, HID);

    pdhg_warp_kernel<<<BATCH / ROWS_PER_BLK, 256, DYN_SMEM>>>(Z, X, out);
}

// round 11
// speedup vs baseline: 1.0657x; 1.0657x over previous
#include <cuda_runtime.h>
#include <cuda_bf16.h>
#include <math.h>

#define N_COMBOS   64
#define N_STRUCTS  512
#define HID        1024
#define BATCH      2048
#define NITERS     60
#define POW_ITERS  30

#define MAX_NNZ_G  32768
#define MAX_LR     96
#define COLCAP     8192
#define ROWS_PER_BLK 8

// ---------------- device scratch ----------------
__device__ float g_Z [BATCH * N_STRUCTS];
__device__ float g_tau;

__device__ __nv_bfloat16 g_Xh[BATCH * N_COMBOS];
__device__ __nv_bfloat16 g_Xl[BATCH * N_COMBOS];
__device__ __nv_bfloat16 g_A1h[BATCH * HID];
__device__ __nv_bfloat16 g_A1l[BATCH * HID];
__device__ __nv_bfloat16 g_A2h[BATCH * HID];
__device__ __nv_bfloat16 g_A2l[BATCH * HID];
__device__ __nv_bfloat16 g_W1hT[HID * N_COMBOS];
__device__ __nv_bfloat16 g_W1lT[HID * N_COMBOS];
__device__ __nv_bfloat16 g_W2hT[HID * HID];
__device__ __nv_bfloat16 g_W2lT[HID * HID];
__device__ __nv_bfloat16 g_W3hT[N_STRUCTS * HID];
__device__ __nv_bfloat16 g_W3lT[N_STRUCTS * HID];

__device__ int            g_row_ptr[N_COMBOS + 1];
__device__ unsigned short g_row_idx[MAX_NNZ_G];
__device__ int            g_col_ptr[N_STRUCTS + 1];
__device__ unsigned char  g_col_idx[MAX_NNZ_G];

__device__ unsigned int   g_ellr[MAX_LR * 32];
__device__ int            g_len_ellr;
__device__ unsigned short g_cp4[N_STRUCTS + 1];
__device__ unsigned char  g_ci4[COLCAP];

// ---------------- split kernels ----------------
__global__ void split_matrix(const float* __restrict__ src,
                             __nv_bfloat16* __restrict__ hi,
                             __nv_bfloat16* __restrict__ lo, int n) {
    int i = blockIdx.x * blockDim.x + threadIdx.x;
    if (i < n) {
        float x = src[i];
        __nv_bfloat16 h = __float2bfloat16(x);
        hi[i] = h;
        lo[i] = __float2bfloat16(x - __bfloat162float(h));
    }
}

// W[K][N] fp32 -> hiT/loT[N][K] bf16
__global__ void split_transpose(const float* __restrict__ W,
                                __nv_bfloat16* __restrict__ hiT,
                                __nv_bfloat16* __restrict__ loT, int K, int N) {
    int i = blockIdx.x * blockDim.x + threadIdx.x;
    if (i < K * N) {
        int k = i / N, n = i % N;
        float x = W[i];
        __nv_bfloat16 h = __float2bfloat16(x);
        hiT[n * K + k] = h;
        loT[n * K + k] = __float2bfloat16(x - __bfloat162float(h));
    }
}

// ---------------- prep (R7, unchanged) ----------------
__global__ __launch_bounds__(512) void prep_kernel(const float* __restrict__ S) {
    __shared__ int cnt[N_STRUCTS];
    int tid = threadIdx.x;

    if (tid < N_COMBOS) {
        int c = 0;
        for (int j = 0; j < N_STRUCTS; j++) if (S[tid * N_STRUCTS + j] != 0.f) c++;
        cnt[tid] = c;
    }
    __syncthreads();
    if (tid == 0) {
        int acc = 0;
        for (int i = 0; i < N_COMBOS; i++) { g_row_ptr[i] = acc; acc += cnt[i]; }
        g_row_ptr[N_COMBOS] = acc;
    }
    __syncthreads();
    if (tid < N_COMBOS) {
        int p = g_row_ptr[tid];
        for (int j = 0; j < N_STRUCTS; j++)
            if (S[tid * N_STRUCTS + j] != 0.f) g_row_idx[p++] = (unsigned short)j;
    }
    __syncthreads();

    {
        int c = 0;
        for (int i = 0; i < N_COMBOS; i++) if (S[i * N_STRUCTS + tid] != 0.f) c++;
        cnt[tid] = c;
    }
    __syncthreads();
    if (tid == 0) {
        int acc = 0;
        for (int j = 0; j < N_STRUCTS; j++) { g_col_ptr[j] = acc; acc += cnt[j]; }
        g_col_ptr[N_STRUCTS] = acc;
    }
    __syncthreads();
    {
        int p = g_col_ptr[tid];
        for (int i = 0; i < N_COMBOS; i++)
            if (S[i * N_STRUCTS + tid] != 0.f) g_col_idx[p++] = (unsigned char)i;
    }
    __syncthreads();

    if (tid < 32) {
        int ra = g_row_ptr[tid],      la = g_row_ptr[tid + 1]  - ra;
        int rb = g_row_ptr[tid + 32], lb = g_row_ptr[tid + 33] - rb;
        int L = la > lb ? la : lb;
        if (L > MAX_LR) L = MAX_LR;
        for (int p = 0; p < MAX_LR; p++) {
            unsigned a = (p < la) ? g_row_idx[ra + p] : 512u;
            unsigned b = (p < lb) ? g_row_idx[rb + p] : 512u;
            g_ellr[p * 32 + tid] = a | (b << 16);
        }
        #pragma unroll
        for (int o = 16; o; o >>= 1) { int v = __shfl_xor_sync(0xffffffffu, L, o); L = v > L ? v : L; }
        if (tid == 0) g_len_ellr = L;
    }
    if (tid == 0) {
        int acc = 0;
        for (int j = 0; j < N_STRUCTS; j++) {
            g_cp4[j] = (unsigned short)acc;
            int l = g_col_ptr[j + 1] - g_col_ptr[j];
            acc += (l + 3) & ~3;
        }
        g_cp4[N_STRUCTS] = (unsigned short)acc;
    }
    __syncthreads();
    {
        int j = tid;
        int o = g_cp4[j];
        int base = g_col_ptr[j];
        int l = g_col_ptr[j + 1] - base;
        int pl = (l + 3) & ~3;
        for (int p = 0; p < pl && (o + p) < COLCAP; p++)
            g_ci4[o + p] = (p < l) ? g_col_idx[base + p] : (unsigned char)64;
    }
}

// ---------------- power iteration (unchanged) ----------------
__global__ __launch_bounds__(512) void power_kernel() {
    __shared__ float v[N_STRUCTS];
    __shared__ float t[N_COMBOS];
    __shared__ float red[16];
    int tid = threadIdx.x;

    v[tid] = 1.0f / sqrtf((float)N_STRUCTS);
    __syncthreads();

    for (int it = 0; it < POW_ITERS; it++) {
        if (tid < N_COMBOS) {
            float s = 0.f;
            int pe = g_row_ptr[tid + 1];
            for (int p = g_row_ptr[tid]; p < pe; p++) s += v[g_row_idx[p]];
            t[tid] = s;
        }
        __syncthreads();
        float w;
        {
            float s = 0.f;
            int pe = g_col_ptr[tid + 1];
            for (int p = g_col_ptr[tid]; p < pe; p++) s += t[g_col_idx[p]];
            w = s + v[tid];
        }
        float sq = w * w;
        #pragma unroll
        for (int o = 16; o; o >>= 1) sq += __shfl_xor_sync(0xffffffffu, sq, o);
        if ((tid & 31) == 0) red[tid >> 5] = sq;
        __syncthreads();
        float tot = 0.f;
        #pragma unroll
        for (int k = 0; k < 16; k++) tot += red[k];
        v[tid] = w / sqrtf(tot);
        __syncthreads();
    }

    if (tid < N_COMBOS) {
        float s = 0.f;
        int pe = g_row_ptr[tid + 1];
        for (int p = g_row_ptr[tid]; p < pe; p++) s += v[g_row_idx[p]];
        t[tid] = s;
    }
    __syncthreads();
    float w;
    {
        float s = 0.f;
        int pe = g_col_ptr[tid + 1];
        for (int p = g_col_ptr[tid]; p < pe; p++) s += t[g_col_idx[p]];
        w = s + v[tid];
    }
    float dq = v[tid] * w;
    #pragma unroll
    for (int o = 16; o; o >>= 1) dq += __shfl_xor_sync(0xffffffffu, dq, o);
    if ((tid & 31) == 0) red[tid >> 5] = dq;
    __syncthreads();
    if (tid == 0) {
        float tot = 0.f;
        #pragma unroll
        for (int k = 0; k < 16; k++) tot += red[k];
        g_tau = 0.9f / sqrtf(tot);
    }
}

// ---------------- bf16-split tensor-core GEMM ----------------
// C = relu(Ah@Bh^T + Ah@Bl^T + Al@Bh^T + bias); optional fp32 C and/or bf16 split out.
// Block tile 128(M) x 64(N), 8 warps (4m x 2n), warp tile 32x32 = 2 x 4 mma tiles.
#define MMA_BF16(c, a, b) asm volatile( \
    "mma.sync.aligned.m16n8k16.row.col.f32.bf16.bf16.f32 " \
    "{%0,%1,%2,%3}, {%4,%5,%6,%7}, {%8,%9}, {%0,%1,%2,%3};" \
    : "+f"(c[0]), "+f"(c[1]), "+f"(c[2]), "+f"(c[3]) \
    : "r"(a[0]), "r"(a[1]), "r"(a[2]), "r"(a[3]), "r"(b[0]), "r"(b[1]))

__global__ __launch_bounds__(256) void gemm_bf16split(
    const __nv_bfloat16* __restrict__ Ah, const __nv_bfloat16* __restrict__ Al,
    const __nv_bfloat16* __restrict__ BhT, const __nv_bfloat16* __restrict__ BlT,
    const float* __restrict__ bias,
    float* __restrict__ C,
    __nv_bfloat16* __restrict__ Ch, __nv_bfloat16* __restrict__ Cl,
    int N, int K)
{
    // 18 bf16 (9 u32) stride rows to stagger frag-load banks
    __shared__ __align__(16) unsigned As[2][128 * 9];
    __shared__ __align__(16) unsigned Bs[2][64 * 9];

    const int tid  = threadIdx.x;
    const int bm   = blockIdx.y * 128;
    const int bn   = blockIdx.x * 64;
    const int wid  = tid >> 5, lane = tid & 31;
    const int wm   = (wid & 3) * 32;
    const int wn   = (wid >> 2) * 32;
    const int g    = lane >> 2;
    const int t4   = lane & 3;

    float acc[2][4][4];
    #pragma unroll
    for (int mt = 0; mt < 2; mt++)
        #pragma unroll
        for (int nt = 0; nt < 4; nt++)
            #pragma unroll
            for (int c = 0; c < 4; c++) acc[mt][nt][c] = 0.f;

    const int ksteps = K >> 4;
    for (int ks = 0; ks < ksteps; ks++) {
        const int k0 = ks << 4;
        // load A tiles (hi+lo): 512 uint4
        #pragma unroll
        for (int rep = 0; rep < 2; rep++) {
            int it = tid + rep * 256;
            int h = it & 1;
            int row = (it >> 1) & 127;
            int prec = it >> 8;
            const __nv_bfloat16* Ap = prec ? Al : Ah;
            uint4 v = *(const uint4*)&Ap[(size_t)(bm + row) * K + k0 + h * 8];
            unsigned* dst = &As[prec][row * 9 + h * 4];
            dst[0] = v.x; dst[1] = v.y; dst[2] = v.z; dst[3] = v.w;
        }
        // load B tiles (hi+lo): 256 uint4
        {
            int it = tid;
            int h = it & 1;
            int row = (it >> 1) & 63;
            int prec = it >> 7;
            const __nv_bfloat16* Bp = prec ? BlT : BhT;
            uint4 v = *(const uint4*)&Bp[(size_t)(bn + row) * K + k0 + h * 8];
            unsigned* dst = &Bs[prec][row * 9 + h * 4];
            dst[0] = v.x; dst[1] = v.y; dst[2] = v.z; dst[3] = v.w;
        }
        __syncthreads();

        unsigned afh[2][4], afl[2][4], bfh[4][2], bfl[4][2];
        #pragma unroll
        for (int mt = 0; mt < 2; mt++) {
            int mb = wm + mt * 16;
            afh[mt][0] = As[0][(mb + g) * 9 + t4];
            afh[mt][1] = As[0][(mb + g + 8) * 9 + t4];
            afh[mt][2] = As[0][(mb + g) * 9 + 4 + t4];
            afh[mt][3] = As[0][(mb + g + 8) * 9 + 4 + t4];
            afl[mt][0] = As[1][(mb + g) * 9 + t4];
            afl[mt][1] = As[1][(mb + g + 8) * 9 + t4];
            afl[mt][2] = As[1][(mb + g) * 9 + 4 + t4];
            afl[mt][3] = As[1][(mb + g + 8) * 9 + 4 + t4];
        }
        #pragma unroll
        for (int nt = 0; nt < 4; nt++) {
            int nb = wn + nt * 8;
            bfh[nt][0] = Bs[0][(nb + g) * 9 + t4];
            bfh[nt][1] = Bs[0][(nb + g) * 9 + 4 + t4];
            bfl[nt][0] = Bs[1][(nb + g) * 9 + t4];
            bfl[nt][1] = Bs[1][(nb + g) * 9 + 4 + t4];
        }
        #pragma unroll
        for (int mt = 0; mt < 2; mt++)
            #pragma unroll
            for (int nt = 0; nt < 4; nt++) {
                MMA_BF16(acc[mt][nt], afh[mt], bfh[nt]);
                MMA_BF16(acc[mt][nt], afh[mt], bfl[nt]);
                MMA_BF16(acc[mt][nt], afl[mt], bfh[nt]);
            }
        __syncthreads();
    }

    // epilogue: bias + relu; optional fp32 and bf16-split outputs
    #pragma unroll
    for (int mt = 0; mt < 2; mt++) {
        #pragma unroll
        for (int nt = 0; nt < 4; nt++) {
            int row0 = bm + wm + mt * 16 + g;
            int col  = bn + wn + nt * 8 + t4 * 2;
            float b0 = bias[col], b1 = bias[col + 1];
            float r00 = acc[mt][nt][0] + b0; r00 = r00 > 0.f ? r00 : 0.f;
            float r01 = acc[mt][nt][1] + b1; r01 = r01 > 0.f ? r01 : 0.f;
            float r10 = acc[mt][nt][2] + b0; r10 = r10 > 0.f ? r10 : 0.f;
            float r11 = acc[mt][nt][3] + b1; r11 = r11 > 0.f ? r11 : 0.f;
            if (C) {
                *(float2*)&C[(size_t)row0 * N + col]       = make_float2(r00, r01);
                *(float2*)&C[(size_t)(row0 + 8) * N + col] = make_float2(r10, r11);
            }
            if (Ch) {
                __nv_bfloat16 h00 = __float2bfloat16(r00), h01 = __float2bfloat16(r01);
                __nv_bfloat16 h10 = __float2bfloat16(r10), h11 = __float2bfloat16(r11);
                __nv_bfloat162 hp0; hp0.x = h00; hp0.y = h01;
                __nv_bfloat162 hp1; hp1.x = h10; hp1.y = h11;
                *(__nv_bfloat162*)&Ch[(size_t)row0 * N + col]       = hp0;
                *(__nv_bfloat162*)&Ch[(size_t)(row0 + 8) * N + col] = hp1;
                __nv_bfloat162 lp0, lp1;
                lp0.x = __float2bfloat16(r00 - __bfloat162float(h00));
                lp0.y = __float2bfloat16(r01 - __bfloat162float(h01));
                lp1.x = __float2bfloat16(r10 - __bfloat162float(h10));
                lp1.y = __float2bfloat16(r11 - __bfloat162float(h11));
                *(__nv_bfloat162*)&Cl[(size_t)row0 * N + col]       = lp0;
                *(__nv_bfloat162*)&Cl[(size_t)(row0 + 8) * N + col] = lp1;
            }
        }
    }
}

// ---------------- PDHG: one WARP per batch row (R7 verbatim) ----------------
__global__ __launch_bounds__(256, 2) void pdhg_warp_kernel(
    const float* __restrict__ Zg, const float* __restrict__ Xg,
    float* __restrict__ out)
{
    constexpr int XB = 516;
    __shared__ unsigned int   s_ellr[MAX_LR * 32];
    __shared__ unsigned short s_cp4[N_STRUCTS + 2];
    __shared__ unsigned char  s_ci4[COLCAP];
    __shared__ float          s_xbar[ROWS_PER_BLK][XB];
    __shared__ float          s_y1[ROWS_PER_BLK][68];

    const int tid = threadIdx.x;
    const int w   = tid >> 5;
    const int l   = tid & 31;
    const int row = blockIdx.x * ROWS_PER_BLK + w;
    const float tau = g_tau;
    const float sigma = tau;
    const int LEN = g_len_ellr;

    for (int p = tid; p < LEN * 32; p += 256) s_ellr[p] = g_ellr[p];
    for (int p = tid; p <= N_STRUCTS; p += 256) s_cp4[p] = g_cp4[p];
    {
        int tot = (g_cp4[N_STRUCTS] + 3) & ~3;
        for (int p = tid * 4; p < tot; p += 1024)
            *(unsigned int*)&s_ci4[p] = *(const unsigned int*)&g_ci4[p];
    }

    float* sx  = s_xbar[w];
    float* sy1 = s_y1[w];

    const float B0 = Xg[row * N_COMBOS + l];
    const float B1 = Xg[row * N_COMBOS + l + 32];
    float yy0 = 0.f, yy1 = 0.f;

    float Zr[16], xr[16], y2[16], xb[16], dq[16];
    #pragma unroll
    for (int q = 0; q < 16; q++) {
        int j = q * 32 + l;
        Zr[q] = Zg[(size_t)row * N_STRUCTS + j];
        xr[q] = 0.f; y2[q] = 0.f; xb[q] = 0.f;
        sx[j] = 0.f;
    }
    if (l < XB - 512) sx[512 + l] = 0.f;
    if (l < 4) sy1[64 + l] = 0.f;
    __syncthreads();

    for (int it = 0; it < NITERS; it++) {
        float s0a = 0.f, s1a = 0.f, s0b = 0.f, s1b = 0.f;
        int p = 0;
        for (; p + 2 <= LEN; p += 2) {
            unsigned ua = s_ellr[p * 32 + l];
            unsigned ub = s_ellr[(p + 1) * 32 + l];
            float va0 = sx[ua & 0xffffu];
            float va1 = sx[ua >> 16];
            float vb0 = sx[ub & 0xffffu];
            float vb1 = sx[ub >> 16];
            s0a += va0; s1a += va1;
            s0b += vb0; s1b += vb1;
        }
        if (p < LEN) {
            unsigned ua = s_ellr[p * 32 + l];
            s0a += sx[ua & 0xffffu];
            s1a += sx[ua >> 16];
        }
        float s0 = s0a + s0b, s1 = s1a + s1b;
        yy0 = fmaxf(fmaf(sigma, s0 - B0, yy0), 0.f);
        yy1 = fmaxf(fmaf(sigma, s1 - B1, yy1), 0.f);
        sy1[l] = yy0;
        sy1[l + 32] = yy1;

        #pragma unroll
        for (int q = 0; q < 16; q++)
            y2[q] = fmaxf(fmaf(-sigma, xb[q], y2[q]), 0.f);
        __syncwarp();

        float sumsq = 0.f;
        #pragma unroll
        for (int q = 0; q < 16; q++) {
            int j = q * 32 + l;
            int o = s_cp4[j], e = s_cp4[j + 1];
            float g = 0.f;
            for (int pp = o; pp < e; pp += 4) {
                unsigned w4 = *(const unsigned int*)&s_ci4[pp];
                g += sy1[w4 & 255u] + sy1[(w4 >> 8) & 255u]
                   + sy1[(w4 >> 16) & 255u] + sy1[w4 >> 24];
            }
            g -= y2[q];
            float v = fmaf(-tau, g, xr[q]);
            float d = v + tau - Zr[q];
            dq[q] = d;
            sumsq = fmaf(d, d, sumsq);
        }
        #pragma unroll
        for (int o = 16; o; o >>= 1) sumsq += __shfl_xor_sync(0xffffffffu, sumsq, o);
        float nrm = sqrtf(sumsq);
        float scale = fmaxf(1.f - tau / fmaxf(nrm, 1e-12f), 0.f);

        #pragma unroll
        for (int q = 0; q < 16; q++) {
            int j = q * 32 + l;
            float xn  = fmaf(scale, dq[q], Zr[q]);
            float xbv = 2.f * xn - xr[q];
            xr[q] = xn;
            xb[q] = xbv;
            sx[j] = xbv;
        }
        __syncwarp();
    }

    #pragma unroll
    for (int q = 0; q < 16; q++)
        out[(size_t)row * N_STRUCTS + q * 32 + l] = xr[q];
}

// ---------------- launch ----------------
extern "C" void kernel_launch(void* const* d_in, const int* in_sizes, int n_in,
                              void* d_out, int out_size) {
    const float* X  = (const float*)d_in[0];
    const float* W1 = (const float*)d_in[1];
    const float* b1 = (const float*)d_in[2];
    const float* W2 = (const float*)d_in[3];
    const float* b2 = (const float*)d_in[4];
    const float* W3 = (const float*)d_in[5];
    const float* b3 = (const float*)d_in[6];
    const float* S  = (const float*)d_in[7];
    float* out = (float*)d_out;

    float *Z;
    __nv_bfloat16 *Xh, *Xl, *A1h, *A1l, *A2h, *A2l;
    __nv_bfloat16 *W1hT, *W1lT, *W2hT, *W2lT, *W3hT, *W3lT;
    cudaGetSymbolAddress((void**)&Z,    g_Z);
    cudaGetSymbolAddress((void**)&Xh,   g_Xh);
    cudaGetSymbolAddress((void**)&Xl,   g_Xl);
    cudaGetSymbolAddress((void**)&A1h,  g_A1h);
    cudaGetSymbolAddress((void**)&A1l,  g_A1l);
    cudaGetSymbolAddress((void**)&A2h,  g_A2h);
    cudaGetSymbolAddress((void**)&A2l,  g_A2l);
    cudaGetSymbolAddress((void**)&W1hT, g_W1hT);
    cudaGetSymbolAddress((void**)&W1lT, g_W1lT);
    cudaGetSymbolAddress((void**)&W2hT, g_W2hT);
    cudaGetSymbolAddress((void**)&W2lT, g_W2lT);
    cudaGetSymbolAddress((void**)&W3hT, g_W3hT);
    cudaGetSymbolAddress((void**)&W3lT, g_W3lT);

    prep_kernel<<<1, 512>>>(S);
    power_kernel<<<1, 512>>>();

    split_matrix<<<(BATCH * N_COMBOS + 255) / 256, 256>>>(X, Xh, Xl, BATCH * N_COMBOS);
    split_transpose<<<(N_COMBOS * HID + 255) / 256, 256>>>(W1, W1hT, W1lT, N_COMBOS, HID);
    split_transpose<<<(HID * HID + 255) / 256, 256>>>(W2, W2hT, W2lT, HID, HID);
    split_transpose<<<(HID * N_STRUCTS + 255) / 256, 256>>>(W3, W3hT, W3lT, HID, N_STRUCTS);

    // L1: [2048,64]@[64,1024]
    gemm_bf16split<<<dim3(HID / 64, BATCH / 128), 256>>>(
        Xh, Xl, W1hT, W1lT, b1, nullptr, A1h, A1l, HID, N_COMBOS);
    // L2: [2048,1024]@[1024,1024]
    gemm_bf16split<<<dim3(HID / 64, BATCH / 128), 256>>>(
        A1h, A1l, W2hT, W2lT, b2, nullptr, A2h, A2l, HID, HID);
    // L3: [2048,1024]@[1024,512] -> fp32 Z
    gemm_bf16split<<<dim3(N_STRUCTS / 64, BATCH / 128), 256>>>(
        A2h, A2l, W3hT, W3lT, b3, Z, nullptr, nullptr, N_STRUCTS, HID);

    pdhg_warp_kernel<<<BATCH / ROWS_PER_BLK, 256>>>(Z, X, out);
}

// round 12
// speedup vs baseline: 1.8697x; 1.7544x over previous
#include <cuda_runtime.h>
#include <cuda_bf16.h>
#include <math.h>

#define N_COMBOS   64
#define N_STRUCTS  512
#define HID        1024
#define BATCH      2048
#define NITERS     60
#define POW_ITERS  30
#define MAX_NNZ_G  32768

// ---- PDHG-MMA shared layout (bytes) ----
#define SB_W    260          // S row stride in u32 words (520 bf16)
#define STB_W   36           // S^T row stride in u32 words (72 bf16)
#define OFF_SB   0                          // 64*520*2   = 66560
#define OFF_STB  66560                      // 512*72*2   = 73728
#define OFF_XBH  140288                     // 16*520*2   = 16640
#define OFF_XBL  156928                     // 16640
#define OFF_Y1H  173568                     // 16*72*2    = 2304
#define OFF_Y1L  175872                     // 2304
#define OFF_PART 178176                     // 8*16*4     = 512
#define DYN_PDHG 178688

// ---------------- device scratch ----------------
__device__ float g_Z [BATCH * N_STRUCTS];
__device__ float g_tau;

__device__ __nv_bfloat16 g_Xh[BATCH * N_COMBOS];
__device__ __nv_bfloat16 g_Xl[BATCH * N_COMBOS];
__device__ __nv_bfloat16 g_A1h[BATCH * HID];
__device__ __nv_bfloat16 g_A1l[BATCH * HID];
__device__ __nv_bfloat16 g_A2h[BATCH * HID];
__device__ __nv_bfloat16 g_A2l[BATCH * HID];
__device__ __nv_bfloat16 g_W1hT[HID * N_COMBOS];
__device__ __nv_bfloat16 g_W1lT[HID * N_COMBOS];
__device__ __nv_bfloat16 g_W2hT[HID * HID];
__device__ __nv_bfloat16 g_W2lT[HID * HID];
__device__ __nv_bfloat16 g_W3hT[N_STRUCTS * HID];
__device__ __nv_bfloat16 g_W3lT[N_STRUCTS * HID];

__device__ __nv_bfloat16 g_Sb [64 * 520];    // S row-major bf16, padded
__device__ __nv_bfloat16 g_STb[512 * 72];    // S^T row-major bf16, padded

__device__ int            g_row_ptr[N_COMBOS + 1];
__device__ unsigned short g_row_idx[MAX_NNZ_G];
__device__ int            g_col_ptr[N_STRUCTS + 1];
__device__ unsigned char  g_col_idx[MAX_NNZ_G];

// ---------------- split kernels ----------------
__global__ void split_matrix(const float* __restrict__ src,
                             __nv_bfloat16* __restrict__ hi,
                             __nv_bfloat16* __restrict__ lo, int n) {
    int i = blockIdx.x * blockDim.x + threadIdx.x;
    if (i < n) {
        float x = src[i];
        __nv_bfloat16 h = __float2bfloat16(x);
        hi[i] = h;
        lo[i] = __float2bfloat16(x - __bfloat162float(h));
    }
}

__global__ void split_transpose(const float* __restrict__ W,
                                __nv_bfloat16* __restrict__ hiT,
                                __nv_bfloat16* __restrict__ loT, int K, int N) {
    int i = blockIdx.x * blockDim.x + threadIdx.x;
    if (i < K * N) {
        int k = i / N, n = i % N;
        float x = W[i];
        __nv_bfloat16 h = __float2bfloat16(x);
        hiT[n * K + k] = h;
        loT[n * K + k] = __float2bfloat16(x - __bfloat162float(h));
    }
}

// build padded bf16 S and S^T
__global__ void build_Sbf16(const float* __restrict__ S) {
    int i = blockIdx.x * blockDim.x + threadIdx.x;
    if (i < 64 * 520) {
        int r = i / 520, c = i % 520;
        g_Sb[i] = (c < 512) ? __float2bfloat16(S[r * 512 + c]) : __float2bfloat16(0.f);
    }
    if (i < 512 * 72) {
        int r = i / 72, c = i % 72;     // r = S col, c = S row
        g_STb[i] = (c < 64) ? __float2bfloat16(S[c * 512 + r]) : __float2bfloat16(0.f);
    }
}

// ---------------- prep: CSR + CSC (for power iteration) ----------------
__global__ __launch_bounds__(512) void prep_kernel(const float* __restrict__ S) {
    __shared__ int cnt[N_STRUCTS];
    int tid = threadIdx.x;

    if (tid < N_COMBOS) {
        int c = 0;
        for (int j = 0; j < N_STRUCTS; j++) if (S[tid * N_STRUCTS + j] != 0.f) c++;
        cnt[tid] = c;
    }
    __syncthreads();
    if (tid == 0) {
        int acc = 0;
        for (int i = 0; i < N_COMBOS; i++) { g_row_ptr[i] = acc; acc += cnt[i]; }
        g_row_ptr[N_COMBOS] = acc;
    }
    __syncthreads();
    if (tid < N_COMBOS) {
        int p = g_row_ptr[tid];
        for (int j = 0; j < N_STRUCTS; j++)
            if (S[tid * N_STRUCTS + j] != 0.f) g_row_idx[p++] = (unsigned short)j;
    }
    __syncthreads();

    {
        int c = 0;
        for (int i = 0; i < N_COMBOS; i++) if (S[i * N_STRUCTS + tid] != 0.f) c++;
        cnt[tid] = c;
    }
    __syncthreads();
    if (tid == 0) {
        int acc = 0;
        for (int j = 0; j < N_STRUCTS; j++) { g_col_ptr[j] = acc; acc += cnt[j]; }
        g_col_ptr[N_STRUCTS] = acc;
    }
    __syncthreads();
    {
        int p = g_col_ptr[tid];
        for (int i = 0; i < N_COMBOS; i++)
            if (S[i * N_STRUCTS + tid] != 0.f) g_col_idx[p++] = (unsigned char)i;
    }
}

// ---------------- power iteration (unchanged) ----------------
__global__ __launch_bounds__(512) void power_kernel() {
    __shared__ float v[N_STRUCTS];
    __shared__ float t[N_COMBOS];
    __shared__ float red[16];
    int tid = threadIdx.x;

    v[tid] = 1.0f / sqrtf((float)N_STRUCTS);
    __syncthreads();

    for (int it = 0; it < POW_ITERS; it++) {
        if (tid < N_COMBOS) {
            float s = 0.f;
            int pe = g_row_ptr[tid + 1];
            for (int p = g_row_ptr[tid]; p < pe; p++) s += v[g_row_idx[p]];
            t[tid] = s;
        }
        __syncthreads();
        float w;
        {
            float s = 0.f;
            int pe = g_col_ptr[tid + 1];
            for (int p = g_col_ptr[tid]; p < pe; p++) s += t[g_col_idx[p]];
            w = s + v[tid];
        }
        float sq = w * w;
        #pragma unroll
        for (int o = 16; o; o >>= 1) sq += __shfl_xor_sync(0xffffffffu, sq, o);
        if ((tid & 31) == 0) red[tid >> 5] = sq;
        __syncthreads();
        float tot = 0.f;
        #pragma unroll
        for (int k = 0; k < 16; k++) tot += red[k];
        v[tid] = w / sqrtf(tot);
        __syncthreads();
    }

    if (tid < N_COMBOS) {
        float s = 0.f;
        int pe = g_row_ptr[tid + 1];
        for (int p = g_row_ptr[tid]; p < pe; p++) s += v[g_row_idx[p]];
        t[tid] = s;
    }
    __syncthreads();
    float w;
    {
        float s = 0.f;
        int pe = g_col_ptr[tid + 1];
        for (int p = g_col_ptr[tid]; p < pe; p++) s += t[g_col_idx[p]];
        w = s + v[tid];
    }
    float dq = v[tid] * w;
    #pragma unroll
    for (int o = 16; o; o >>= 1) dq += __shfl_xor_sync(0xffffffffu, dq, o);
    if ((tid & 31) == 0) red[tid >> 5] = dq;
    __syncthreads();
    if (tid == 0) {
        float tot = 0.f;
        #pragma unroll
        for (int k = 0; k < 16; k++) tot += red[k];
        g_tau = 0.9f / sqrtf(tot);
    }
}

// ---------------- MMA macro (R11-verified) ----------------
#define MMA_BF16(c, a, b) asm volatile( \
    "mma.sync.aligned.m16n8k16.row.col.f32.bf16.bf16.f32 " \
    "{%0,%1,%2,%3}, {%4,%5,%6,%7}, {%8,%9}, {%0,%1,%2,%3};" \
    : "+f"(c[0]), "+f"(c[1]), "+f"(c[2]), "+f"(c[3]) \
    : "r"(a[0]), "r"(a[1]), "r"(a[2]), "r"(a[3]), "r"(b[0]), "r"(b[1]))

__device__ __forceinline__ unsigned pack_bf16x2(float v0, float v1) {
    __nv_bfloat162 b2;
    b2.x = __float2bfloat16(v0);
    b2.y = __float2bfloat16(v1);
    return *(unsigned*)&b2;
}
__device__ __forceinline__ unsigned pack_bf16x2_res(float v0, float v1, unsigned hibits) {
    __nv_bfloat162 hb = *(__nv_bfloat162*)&hibits;
    __nv_bfloat162 b2;
    b2.x = __float2bfloat16(v0 - __bfloat162float(hb.x));
    b2.y = __float2bfloat16(v1 - __bfloat162float(hb.y));
    return *(unsigned*)&b2;
}

// ---------------- bf16-split tensor-core GEMM (R11 verbatim) ----------------
__global__ __launch_bounds__(256) void gemm_bf16split(
    const __nv_bfloat16* __restrict__ Ah, const __nv_bfloat16* __restrict__ Al,
    const __nv_bfloat16* __restrict__ BhT, const __nv_bfloat16* __restrict__ BlT,
    const float* __restrict__ bias,
    float* __restrict__ C,
    __nv_bfloat16* __restrict__ Ch, __nv_bfloat16* __restrict__ Cl,
    int N, int K)
{
    __shared__ __align__(16) unsigned As[2][128 * 9];
    __shared__ __align__(16) unsigned Bs[2][64 * 9];

    const int tid  = threadIdx.x;
    const int bm   = blockIdx.y * 128;
    const int bn   = blockIdx.x * 64;
    const int wid  = tid >> 5, lane = tid & 31;
    const int wm   = (wid & 3) * 32;
    const int wn   = (wid >> 2) * 32;
    const int g    = lane >> 2;
    const int t4   = lane & 3;

    float acc[2][4][4];
    #pragma unroll
    for (int mt = 0; mt < 2; mt++)
        #pragma unroll
        for (int nt = 0; nt < 4; nt++)
            #pragma unroll
            for (int c = 0; c < 4; c++) acc[mt][nt][c] = 0.f;

    const int ksteps = K >> 4;
    for (int ks = 0; ks < ksteps; ks++) {
        const int k0 = ks << 4;
        #pragma unroll
        for (int rep = 0; rep < 2; rep++) {
            int it = tid + rep * 256;
            int h = it & 1;
            int row = (it >> 1) & 127;
            int prec = it >> 8;
            const __nv_bfloat16* Ap = prec ? Al : Ah;
            uint4 v = *(const uint4*)&Ap[(size_t)(bm + row) * K + k0 + h * 8];
            unsigned* dst = &As[prec][row * 9 + h * 4];
            dst[0] = v.x; dst[1] = v.y; dst[2] = v.z; dst[3] = v.w;
        }
        {
            int it = tid;
            int h = it & 1;
            int row = (it >> 1) & 63;
            int prec = it >> 7;
            const __nv_bfloat16* Bp = prec ? BlT : BhT;
            uint4 v = *(const uint4*)&Bp[(size_t)(bn + row) * K + k0 + h * 8];
            unsigned* dst = &Bs[prec][row * 9 + h * 4];
            dst[0] = v.x; dst[1] = v.y; dst[2] = v.z; dst[3] = v.w;
        }
        __syncthreads();

        unsigned afh[2][4], afl[2][4], bfh[4][2], bfl[4][2];
        #pragma unroll
        for (int mt = 0; mt < 2; mt++) {
            int mb = wm + mt * 16;
            afh[mt][0] = As[0][(mb + g) * 9 + t4];
            afh[mt][1] = As[0][(mb + g + 8) * 9 + t4];
            afh[mt][2] = As[0][(mb + g) * 9 + 4 + t4];
            afh[mt][3] = As[0][(mb + g + 8) * 9 + 4 + t4];
            afl[mt][0] = As[1][(mb + g) * 9 + t4];
            afl[mt][1] = As[1][(mb + g + 8) * 9 + t4];
            afl[mt][2] = As[1][(mb + g) * 9 + 4 + t4];
            afl[mt][3] = As[1][(mb + g + 8) * 9 + 4 + t4];
        }
        #pragma unroll
        for (int nt = 0; nt < 4; nt++) {
            int nb = wn + nt * 8;
            bfh[nt][0] = Bs[0][(nb + g) * 9 + t4];
            bfh[nt][1] = Bs[0][(nb + g) * 9 + 4 + t4];
            bfl[nt][0] = Bs[1][(nb + g) * 9 + t4];
            bfl[nt][1] = Bs[1][(nb + g) * 9 + 4 + t4];
        }
        #pragma unroll
        for (int mt = 0; mt < 2; mt++)
            #pragma unroll
            for (int nt = 0; nt < 4; nt++) {
                MMA_BF16(acc[mt][nt], afh[mt], bfh[nt]);
                MMA_BF16(acc[mt][nt], afh[mt], bfl[nt]);
                MMA_BF16(acc[mt][nt], afl[mt], bfh[nt]);
            }
        __syncthreads();
    }

    #pragma unroll
    for (int mt = 0; mt < 2; mt++) {
        #pragma unroll
        for (int nt = 0; nt < 4; nt++) {
            int row0 = bm + wm + mt * 16 + g;
            int col  = bn + wn + nt * 8 + t4 * 2;
            float b0 = bias[col], b1 = bias[col + 1];
            float r00 = acc[mt][nt][0] + b0; r00 = r00 > 0.f ? r00 : 0.f;
            float r01 = acc[mt][nt][1] + b1; r01 = r01 > 0.f ? r01 : 0.f;
            float r10 = acc[mt][nt][2] + b0; r10 = r10 > 0.f ? r10 : 0.f;
            float r11 = acc[mt][nt][3] + b1; r11 = r11 > 0.f ? r11 : 0.f;
            if (C) {
                *(float2*)&C[(size_t)row0 * N + col]       = make_float2(r00, r01);
                *(float2*)&C[(size_t)(row0 + 8) * N + col] = make_float2(r10, r11);
            }
            if (Ch) {
                unsigned h0 = pack_bf16x2(r00, r01);
                unsigned h1 = pack_bf16x2(r10, r11);
                *(unsigned*)&Ch[(size_t)row0 * N + col]       = h0;
                *(unsigned*)&Ch[(size_t)(row0 + 8) * N + col] = h1;
                *(unsigned*)&Cl[(size_t)row0 * N + col]       = pack_bf16x2_res(r00, r01, h0);
                *(unsigned*)&Cl[(size_t)(row0 + 8) * N + col] = pack_bf16x2_res(r10, r11, h1);
            }
        }
    }
}

// ---------------- PDHG via dense tensor-core MMA: 16 batch rows / block ----------------
__global__ __launch_bounds__(256, 1) void pdhg_mma_kernel(
    const float* __restrict__ Zg, const float* __restrict__ Xg,
    float* __restrict__ out)
{
    extern __shared__ __align__(16) char dyn[];
    unsigned* Sb_u  = (unsigned*)(dyn + OFF_SB);    // [64][260]
    unsigned* STb_u = (unsigned*)(dyn + OFF_STB);   // [512][36]
    unsigned* xbh_u = (unsigned*)(dyn + OFF_XBH);   // [16][260]
    unsigned* xbl_u = (unsigned*)(dyn + OFF_XBL);
    unsigned* y1h_u = (unsigned*)(dyn + OFF_Y1H);   // [16][36]
    unsigned* y1l_u = (unsigned*)(dyn + OFF_Y1L);
    float*    part  = (float*)(dyn + OFF_PART);     // [8][16]

    const int tid = threadIdx.x;
    const int w = tid >> 5, lane = tid & 31;
    const int g = lane >> 2, t4 = lane & 3;
    const int row0 = blockIdx.x * 16;
    const float tau = g_tau, sigma = tau;

    // copy S / S^T
    {
        const uint4* src = (const uint4*)g_Sb;
        uint4* dst = (uint4*)Sb_u;
        for (int p = tid; p < (64 * 520 * 2) / 16; p += 256) dst[p] = src[p];
        const uint4* src2 = (const uint4*)g_STb;
        uint4* dst2 = (uint4*)STb_u;
        for (int p = tid; p < (512 * 72 * 2) / 16; p += 256) dst2[p] = src2[p];
    }
    // zero xbar hi/lo
    for (int p = tid; p < 16 * 260; p += 256) { xbh_u[p] = 0u; xbl_u[p] = 0u; }

    // per-thread state: idx = tt*4 + e  (e: 0,1 = batch g cols 2t4,2t4+1; 2,3 = batch g+8)
    float x[32], y2[32], Zr[32];
    #pragma unroll
    for (int tt = 0; tt < 8; tt++) {
        int col = w * 8 + tt * 64 + 2 * t4;
        float2 z0 = *(const float2*)&Zg[(size_t)(row0 + g) * N_STRUCTS + col];
        float2 z1 = *(const float2*)&Zg[(size_t)(row0 + g + 8) * N_STRUCTS + col];
        Zr[tt * 4 + 0] = z0.x; Zr[tt * 4 + 1] = z0.y;
        Zr[tt * 4 + 2] = z1.x; Zr[tt * 4 + 3] = z1.y;
        #pragma unroll
        for (int e = 0; e < 4; e++) { x[tt * 4 + e] = 0.f; y2[tt * 4 + e] = 0.f; }
    }
    float y1v[4] = {0.f, 0.f, 0.f, 0.f};
    float Bc[4];
    Bc[0] = Xg[(row0 + g) * N_COMBOS + w * 8 + 2 * t4];
    Bc[1] = Xg[(row0 + g) * N_COMBOS + w * 8 + 2 * t4 + 1];
    Bc[2] = Xg[(row0 + g + 8) * N_COMBOS + w * 8 + 2 * t4];
    Bc[3] = Xg[(row0 + g + 8) * N_COMBOS + w * 8 + 2 * t4 + 1];
    __syncthreads();

    for (int it = 0; it < NITERS; it++) {
        // ---- dir1: t = xbar^T @ S^T ; warp w owns S-rows w*8..w*8+7 ----
        float c1a[4] = {0.f, 0.f, 0.f, 0.f};
        #pragma unroll 4
        for (int ks = 0; ks < 32; ks++) {
            int kw = ks * 8;
            int a0 = g * SB_W + kw + t4, a1 = (g + 8) * SB_W + kw + t4;
            unsigned ah[4], al[4], bs[2];
            ah[0] = xbh_u[a0]; ah[1] = xbh_u[a1]; ah[2] = xbh_u[a0 + 4]; ah[3] = xbh_u[a1 + 4];
            al[0] = xbl_u[a0]; al[1] = xbl_u[a1]; al[2] = xbl_u[a0 + 4]; al[3] = xbl_u[a1 + 4];
            int br = (w * 8 + g) * SB_W + kw + t4;
            bs[0] = Sb_u[br]; bs[1] = Sb_u[br + 4];
            MMA_BF16(c1a, ah, bs);
            MMA_BF16(c1a, al, bs);
        }
        // y1 update (registers), write hi/lo to shared
        #pragma unroll
        for (int e = 0; e < 4; e++)
            y1v[e] = fmaxf(fmaf(sigma, c1a[e] - Bc[e], y1v[e]), 0.f);
        {
            int w0 = g * STB_W + w * 4 + t4;
            int w1 = (g + 8) * STB_W + w * 4 + t4;
            unsigned h0 = pack_bf16x2(y1v[0], y1v[1]);
            unsigned h1 = pack_bf16x2(y1v[2], y1v[3]);
            y1h_u[w0] = h0;
            y1h_u[w1] = h1;
            y1l_u[w0] = pack_bf16x2_res(y1v[0], y1v[1], h0);
            y1l_u[w1] = pack_bf16x2_res(y1v[2], y1v[3], h1);
        }
        __syncthreads();

        // ---- dir2: gmat = y1^T @ S ; warp w owns col tiles w*8 + tt*64 ----
        float c2a[8][4];
        #pragma unroll
        for (int tt = 0; tt < 8; tt++)
            #pragma unroll
            for (int e = 0; e < 4; e++) c2a[tt][e] = 0.f;
        #pragma unroll
        for (int ks = 0; ks < 4; ks++) {
            int kw = ks * 8;
            int a0 = g * STB_W + kw + t4, a1 = (g + 8) * STB_W + kw + t4;
            unsigned ah[4], al[4];
            ah[0] = y1h_u[a0]; ah[1] = y1h_u[a1]; ah[2] = y1h_u[a0 + 4]; ah[3] = y1h_u[a1 + 4];
            al[0] = y1l_u[a0]; al[1] = y1l_u[a1]; al[2] = y1l_u[a0 + 4]; al[3] = y1l_u[a1 + 4];
            #pragma unroll
            for (int tt = 0; tt < 8; tt++) {
                int br = (w * 8 + tt * 64 + g) * STB_W + kw + t4;
                unsigned bs[2] = { STb_u[br], STb_u[br + 4] };
                MMA_BF16(c2a[tt], ah, bs);
                MMA_BF16(c2a[tt], al, bs);
            }
        }

        // ---- elementwise: d, per-batch sumsq ----
        float sq0 = 0.f, sq1 = 0.f;
        #pragma unroll
        for (int tt = 0; tt < 8; tt++) {
            #pragma unroll
            for (int e = 0; e < 4; e++) {
                int idx = tt * 4 + e;
                float gv = c2a[tt][e] - y2[idx];
                float v  = fmaf(-tau, gv, x[idx]);
                float d  = v + tau - Zr[idx];
                c2a[tt][e] = d;
                if (e < 2) sq0 = fmaf(d, d, sq0); else sq1 = fmaf(d, d, sq1);
            }
        }
        sq0 += __shfl_xor_sync(0xffffffffu, sq0, 1);
        sq0 += __shfl_xor_sync(0xffffffffu, sq0, 2);
        sq1 += __shfl_xor_sync(0xffffffffu, sq1, 1);
        sq1 += __shfl_xor_sync(0xffffffffu, sq1, 2);
        if (t4 == 0) { part[w * 16 + g] = sq0; part[w * 16 + g + 8] = sq1; }
        __syncthreads();

        float tot0 = 0.f, tot1 = 0.f;
        #pragma unroll
        for (int ww = 0; ww < 8; ww++) {
            tot0 += part[ww * 16 + g];
            tot1 += part[ww * 16 + g + 8];
        }
        float sc0 = fmaxf(1.f - tau / fmaxf(sqrtf(tot0), 1e-12f), 0.f);
        float sc1 = fmaxf(1.f - tau / fmaxf(sqrtf(tot1), 1e-12f), 0.f);

        // ---- prox, xbar, pre-applied y2 update, store xbar hi/lo ----
        #pragma unroll
        for (int tt = 0; tt < 8; tt++) {
            float xb0, xb1, xb2, xb3;
            {
                int i0 = tt * 4 + 0, i1 = tt * 4 + 1;
                float xn0 = fmaf(sc0, c2a[tt][0], Zr[i0]);
                float xn1 = fmaf(sc0, c2a[tt][1], Zr[i1]);
                xb0 = 2.f * xn0 - x[i0]; xb1 = 2.f * xn1 - x[i1];
                x[i0] = xn0; x[i1] = xn1;
                y2[i0] = fmaxf(fmaf(-sigma, xb0, y2[i0]), 0.f);
                y2[i1] = fmaxf(fmaf(-sigma, xb1, y2[i1]), 0.f);
            }
            {
                int i2 = tt * 4 + 2, i3 = tt * 4 + 3;
                float xn2 = fmaf(sc1, c2a[tt][2], Zr[i2]);
                float xn3 = fmaf(sc1, c2a[tt][3], Zr[i3]);
                xb2 = 2.f * xn2 - x[i2]; xb3 = 2.f * xn3 - x[i3];
                x[i2] = xn2; x[i3] = xn3;
                y2[i2] = fmaxf(fmaf(-sigma, xb2, y2[i2]), 0.f);
                y2[i3] = fmaxf(fmaf(-sigma, xb3, y2[i3]), 0.f);
            }
            int w0 = g * SB_W + tt * 32 + w * 4 + t4;
            int w1 = (g + 8) * SB_W + tt * 32 + w * 4 + t4;
            unsigned h0 = pack_bf16x2(xb0, xb1);
            unsigned h1 = pack_bf16x2(xb2, xb3);
            xbh_u[w0] = h0;
            xbh_u[w1] = h1;
            xbl_u[w0] = pack_bf16x2_res(xb0, xb1, h0);
            xbl_u[w1] = pack_bf16x2_res(xb2, xb3, h1);
        }
        __syncthreads();
    }

    // write out x
    #pragma unroll
    for (int tt = 0; tt < 8; tt++) {
        int col = w * 8 + tt * 64 + 2 * t4;
        *(float2*)&out[(size_t)(row0 + g) * N_STRUCTS + col] =
            make_float2(x[tt * 4 + 0], x[tt * 4 + 1]);
        *(float2*)&out[(size_t)(row0 + g + 8) * N_STRUCTS + col] =
            make_float2(x[tt * 4 + 2], x[tt * 4 + 3]);
    }
}

// ---------------- launch ----------------
extern "C" void kernel_launch(void* const* d_in, const int* in_sizes, int n_in,
                              void* d_out, int out_size) {
    const float* X  = (const float*)d_in[0];
    const float* W1 = (const float*)d_in[1];
    const float* b1 = (const float*)d_in[2];
    const float* W2 = (const float*)d_in[3];
    const float* b2 = (const float*)d_in[4];
    const float* W3 = (const float*)d_in[5];
    const float* b3 = (const float*)d_in[6];
    const float* S  = (const float*)d_in[7];
    float* out = (float*)d_out;

    float *Z;
    __nv_bfloat16 *Xh, *Xl, *A1h, *A1l, *A2h, *A2l;
    __nv_bfloat16 *W1hT, *W1lT, *W2hT, *W2lT, *W3hT, *W3lT;
    cudaGetSymbolAddress((void**)&Z,    g_Z);
    cudaGetSymbolAddress((void**)&Xh,   g_Xh);
    cudaGetSymbolAddress((void**)&Xl,   g_Xl);
    cudaGetSymbolAddress((void**)&A1h,  g_A1h);
    cudaGetSymbolAddress((void**)&A1l,  g_A1l);
    cudaGetSymbolAddress((void**)&A2h,  g_A2h);
    cudaGetSymbolAddress((void**)&A2l,  g_A2l);
    cudaGetSymbolAddress((void**)&W1hT, g_W1hT);
    cudaGetSymbolAddress((void**)&W1lT, g_W1lT);
    cudaGetSymbolAddress((void**)&W2hT, g_W2hT);
    cudaGetSymbolAddress((void**)&W2lT, g_W2lT);
    cudaGetSymbolAddress((void**)&W3hT, g_W3hT);
    cudaGetSymbolAddress((void**)&W3lT, g_W3lT);

    static int smem_set = 0;
    if (!smem_set) {
        cudaFuncSetAttribute(pdhg_mma_kernel,
                             cudaFuncAttributeMaxDynamicSharedMemorySize, DYN_PDHG);
        smem_set = 1;
    }

    prep_kernel<<<1, 512>>>(S);
    power_kernel<<<1, 512>>>();
    build_Sbf16<<<(512 * 72 + 511) / 512, 512>>>(S);

    split_matrix<<<(BATCH * N_COMBOS + 255) / 256, 256>>>(X, Xh, Xl, BATCH * N_COMBOS);
    split_transpose<<<(N_COMBOS * HID + 255) / 256, 256>>>(W1, W1hT, W1lT, N_COMBOS, HID);
    split_transpose<<<(HID * HID + 255) / 256, 256>>>(W2, W2hT, W2lT, HID, HID);
    split_transpose<<<(HID * N_STRUCTS + 255) / 256, 256>>>(W3, W3hT, W3lT, HID, N_STRUCTS);

    gemm_bf16split<<<dim3(HID / 64, BATCH / 128), 256>>>(
        Xh, Xl, W1hT, W1lT, b1, nullptr, A1h, A1l, HID, N_COMBOS);
    gemm_bf16split<<<dim3(HID / 64, BATCH / 128), 256>>>(
        A1h, A1l, W2hT, W2lT, b2, nullptr, A2h, A2l, HID, HID);
    gemm_bf16split<<<dim3(N_STRUCTS / 64, BATCH / 128), 256>>>(
        A2h, A2l, W3hT, W3lT, b3, Z, nullptr, nullptr, N_STRUCTS, HID);

    pdhg_mma_kernel<<<BATCH / 16, 256, DYN_PDHG>>>(Z, X, out);
}